// round 1
// baseline (speedup 1.0000x reference)
#include <cuda_runtime.h>
#include <cstdint>

// Problem constants
#define BATCH 1024
#define SEQ   512
#define NF    64      // input features
#define H     128     // hidden
#define G4    512     // 4*H gate columns
#define NOUT  128

// Kernel config
#define M        8            // batch rows per CTA
#define NCTA     128          // 1024/8
#define NTHR     256
#define S_CACHE  28           // W_hh k-rows cached in smem
#define KSM      (NF + S_CACHE)   // 92 rows of fp32 weights resident in smem
#define GBPAD    9            // gbuf row padding (conflict-free, 9 coprime 32)

// smem layout (floats)
#define OFF_WSM   0
#define OFF_XS    (KSM * G4)                 // [2][NF][M]
#define OFF_HXH   (OFF_XS + 2 * NF * M)      // [H][M]
#define OFF_GBUF  (OFF_HXH + H * M)          // [G4][GBPAD]
#define SMEM_FLOATS (OFF_GBUF + G4 * GBPAD)
#define SMEM_BYTES  (SMEM_FLOATS * 4)        // 215040 bytes

typedef unsigned long long ull;

// transposed combined weights: g_WT[k][c], k in [0,192): k<64 -> W_ih, else W_hh
__device__ float g_WT[(NF + H) * G4];

// ---------------- packed f32x2 helpers ----------------
__device__ __forceinline__ void ffma2(ull& acc, ull a, ull b) {
    asm("fma.rn.f32x2 %0, %1, %2, %0;" : "+l"(acc) : "l"(a), "l"(b));
}
__device__ __forceinline__ ull pack2(float lo, float hi) {
    ull r; asm("mov.b64 %0, {%1, %2};" : "=l"(r) : "f"(lo), "f"(hi)); return r;
}
__device__ __forceinline__ void unpack2(ull v, float& lo, float& hi) {
    asm("mov.b64 {%0, %1}, %2;" : "=f"(lo), "=f"(hi) : "l"(v));
}
// from packed (w0,w1) make (w0,w0) and (w1,w1)
__device__ __forceinline__ void dup2(ull w2, ull& d0, ull& d1) {
    asm("{\n\t"
        ".reg .f32 w0, w1;\n\t"
        "mov.b64 {w0, w1}, %2;\n\t"
        "mov.b64 %0, {w0, w0};\n\t"
        "mov.b64 %1, {w1, w1};\n\t"
        "}" : "=l"(d0), "=l"(d1) : "l"(w2));
}

// ---------------- accurate-ish activations (ex2 ~2ulp, rcp ~1ulp) ----------------
__device__ __forceinline__ float ex2f(float x) { float r; asm("ex2.approx.f32 %0, %1;" : "=f"(r) : "f"(x)); return r; }
__device__ __forceinline__ float rcpf(float x) { float r; asm("rcp.approx.f32 %0, %1;" : "=f"(r) : "f"(x)); return r; }
__device__ __forceinline__ float sigmf(float x) {
    return rcpf(1.0f + ex2f(-1.4426950408889634f * x));  // 1/(1+2^(-x*log2e))
}
__device__ __forceinline__ float tanhf_acc(float x) {
    // tanh(x) = 2*sigmoid(2x) - 1
    return fmaf(2.0f, rcpf(1.0f + ex2f(-2.8853900817779268f * x)), -1.0f);
}
__device__ __forceinline__ float act(float v, bool isTanh) {
    return isTanh ? tanhf_acc(v) : sigmf(v);
}

// ---------------- one-time weight transpose ----------------
__global__ void prep_kernel(const float* __restrict__ W_ih, const float* __restrict__ W_hh) {
    int idx = blockIdx.x * blockDim.x + threadIdx.x;  // over 192*512, c fastest
    if (idx >= (NF + H) * G4) return;
    int k = idx / G4;
    int c = idx - k * G4;
    float v = (k < NF) ? W_ih[c * NF + k] : W_hh[c * H + (k - NF)];
    g_WT[idx] = v;
}

// ---------------- persistent fused LSTM kernel ----------------
__global__ void __launch_bounds__(NTHR, 1)
lstm_kernel(const float* __restrict__ x,
            const float* __restrict__ b_ih, const float* __restrict__ b_hh,
            const float* __restrict__ W_out, const float* __restrict__ b_out,
            float* __restrict__ out)
{
    extern __shared__ float sm[];
    float* Wsm  = sm + OFF_WSM;    // [KSM][G4]
    float* xs   = sm + OFF_XS;     // [2][NF][M]
    float* hxh  = sm + OFF_HXH;    // [H][M]
    float* gbuf = sm + OFF_GBUF;   // [G4][GBPAD]

    const int tid = threadIdx.x;
    const int b0  = blockIdx.x * M;

    // ---- prologue: stage resident weights (coalesced) ----
    {
        const float4* src = (const float4*)g_WT;
        float4*       dst = (float4*)Wsm;
        const int n = KSM * G4 / 4;          // 11776, exact multiple of NTHR
        for (int i = tid; i < n; i += NTHR) dst[i] = src[i];
    }
    for (int i = tid; i < H * M; i += NTHR) hxh[i] = 0.0f;

    // my two gate columns
    const int c0 = 2 * tid;                      // 0..510
    ull bias0, bias1;
    {
        float bb0 = b_ih[c0]     + b_hh[c0];
        float bb1 = b_ih[c0 + 1] + b_hh[c0 + 1];
        bias0 = pack2(bb0, bb0);
        bias1 = pack2(bb1, bb1);
    }

    // x loader identity (tid < 128): row lm, float4-chunk lq
    const int lm = tid >> 4;                     // 0..7  (for tid<128)
    const int lq = tid & 15;                     // 0..15
    const float* xrow = x + (size_t)(b0 + (lm & 7)) * SEQ * NF;

    // phase-2 identity: h column hc, row group rg (rows 4rg..4rg+3)
    const int hc = tid & 127;
    const int rg = tid >> 7;
    const int r0 = 4 * rg;
    float cst[4] = {0.f, 0.f, 0.f, 0.f};

    // stage x(t=0)
    if (tid < 128) {
        float4 xv = *(const float4*)(xrow + 4 * lq);
        float* xd = xs;  // buffer 0
        xd[(4 * lq + 0) * M + lm] = xv.x;
        xd[(4 * lq + 1) * M + lm] = xv.y;
        xd[(4 * lq + 2) * M + lm] = xv.z;
        xd[(4 * lq + 3) * M + lm] = xv.w;
    }
    __syncthreads();

    const bool isTanh = ((c0 >> 7) == 2);   // gate g columns 256..383

    for (int t = 0; t < SEQ; ++t) {
        const float* xsb = xs + (t & 1) * (NF * M);

        // prefetch next timestep's x (latency hidden under the matvec)
        float4 xv = make_float4(0.f, 0.f, 0.f, 0.f);
        const bool doPre = (tid < 128) && (t + 1 < SEQ);
        if (doPre) xv = *(const float4*)(xrow + (size_t)(t + 1) * NF + 4 * lq);

        // gate accumulators: [2 cols][4 row-pairs], packed rows
        ull a00 = bias0, a01 = bias0, a02 = bias0, a03 = bias0;
        ull a10 = bias1, a11 = bias1, a12 = bias1, a13 = bias1;

        // ---- x contribution: k in [0,64), weights resident ----
        #pragma unroll 8
        for (int k = 0; k < NF; ++k) {
            ull w2 = *(const ull*)(Wsm + k * G4 + c0);
            ull d0, d1; dup2(w2, d0, d1);
            ulonglong2 hA = *(const ulonglong2*)(xsb + k * M);      // rows 0..3
            ulonglong2 hB = *(const ulonglong2*)(xsb + k * M + 4);  // rows 4..7
            ffma2(a00, hA.x, d0); ffma2(a01, hA.y, d0);
            ffma2(a02, hB.x, d0); ffma2(a03, hB.y, d0);
            ffma2(a10, hA.x, d1); ffma2(a11, hA.y, d1);
            ffma2(a12, hB.x, d1); ffma2(a13, hB.y, d1);
        }
        // ---- h contribution, smem-cached part: k in [0,S_CACHE) ----
        #pragma unroll 4
        for (int k = 0; k < S_CACHE; ++k) {
            ull w2 = *(const ull*)(Wsm + (NF + k) * G4 + c0);
            ull d0, d1; dup2(w2, d0, d1);
            ulonglong2 hA = *(const ulonglong2*)(hxh + k * M);
            ulonglong2 hB = *(const ulonglong2*)(hxh + k * M + 4);
            ffma2(a00, hA.x, d0); ffma2(a01, hA.y, d0);
            ffma2(a02, hB.x, d0); ffma2(a03, hB.y, d0);
            ffma2(a10, hA.x, d1); ffma2(a11, hA.y, d1);
            ffma2(a12, hB.x, d1); ffma2(a13, hB.y, d1);
        }
        // ---- h contribution, L2-streamed part: k in [S_CACHE,128) ----
        {
            const ull* wg = (const ull*)(g_WT + KSM * G4) + tid;
            #pragma unroll 4
            for (int k = S_CACHE; k < H; ++k) {
                ull w2 = __ldg(wg); wg += (G4 / 2);
                ull d0, d1; dup2(w2, d0, d1);
                ulonglong2 hA = *(const ulonglong2*)(hxh + k * M);
                ulonglong2 hB = *(const ulonglong2*)(hxh + k * M + 4);
                ffma2(a00, hA.x, d0); ffma2(a01, hA.y, d0);
                ffma2(a02, hB.x, d0); ffma2(a03, hB.y, d0);
                ffma2(a10, hA.x, d1); ffma2(a11, hA.y, d1);
                ffma2(a12, hB.x, d1); ffma2(a13, hB.y, d1);
            }
        }

        // ---- activations -> gbuf (warp-uniform gate type, no divergence) ----
        {
            float v0, v1;
            float* gb0 = gbuf + c0 * GBPAD;
            float* gb1 = gbuf + (c0 + 1) * GBPAD;
            unpack2(a00, v0, v1); gb0[0] = act(v0, isTanh); gb0[1] = act(v1, isTanh);
            unpack2(a01, v0, v1); gb0[2] = act(v0, isTanh); gb0[3] = act(v1, isTanh);
            unpack2(a02, v0, v1); gb0[4] = act(v0, isTanh); gb0[5] = act(v1, isTanh);
            unpack2(a03, v0, v1); gb0[6] = act(v0, isTanh); gb0[7] = act(v1, isTanh);
            unpack2(a10, v0, v1); gb1[0] = act(v0, isTanh); gb1[1] = act(v1, isTanh);
            unpack2(a11, v0, v1); gb1[2] = act(v0, isTanh); gb1[3] = act(v1, isTanh);
            unpack2(a12, v0, v1); gb1[4] = act(v0, isTanh); gb1[5] = act(v1, isTanh);
            unpack2(a13, v0, v1); gb1[6] = act(v0, isTanh); gb1[7] = act(v1, isTanh);
        }
        __syncthreads();

        // ---- phase 2: state update (c in registers, h -> smem transposed) ----
        {
            const float* gb_i = gbuf + (hc        ) * GBPAD;
            const float* gb_f = gbuf + (hc + 128  ) * GBPAD;
            const float* gb_g = gbuf + (hc + 256  ) * GBPAD;
            const float* gb_o = gbuf + (hc + 384  ) * GBPAD;
            float hv[4];
            #pragma unroll
            for (int j = 0; j < 4; ++j) {
                float iv = gb_i[r0 + j];
                float fv = gb_f[r0 + j];
                float gv = gb_g[r0 + j];
                float ov = gb_o[r0 + j];
                cst[j] = fmaf(fv, cst[j], iv * gv);
                hv[j]  = ov * tanhf_acc(cst[j]);
            }
            *(float4*)(hxh + hc * M + r0) = make_float4(hv[0], hv[1], hv[2], hv[3]);

            if (doPre) {
                float* xd = xs + ((t + 1) & 1) * (NF * M);
                xd[(4 * lq + 0) * M + lm] = xv.x;
                xd[(4 * lq + 1) * M + lm] = xv.y;
                xd[(4 * lq + 2) * M + lm] = xv.z;
                xd[(4 * lq + 3) * M + lm] = xv.w;
            }
        }
        __syncthreads();
    }

    // ---- output projection: out[b0+r][oc] = h . W_out[oc,:] + b_out[oc] ----
    {
        const int oc = hc;
        float acc0, acc1, acc2, acc3;
        acc0 = acc1 = acc2 = acc3 = b_out[oc];
        const float* wrow = W_out + oc * H;
        #pragma unroll 4
        for (int k = 0; k < H; k += 4) {
            float4 w  = *(const float4*)(wrow + k);
            float4 h0 = *(const float4*)(hxh + (k + 0) * M + r0);
            float4 h1 = *(const float4*)(hxh + (k + 1) * M + r0);
            float4 h2 = *(const float4*)(hxh + (k + 2) * M + r0);
            float4 h3 = *(const float4*)(hxh + (k + 3) * M + r0);
            acc0 = fmaf(w.x, h0.x, acc0); acc1 = fmaf(w.x, h0.y, acc1);
            acc2 = fmaf(w.x, h0.z, acc2); acc3 = fmaf(w.x, h0.w, acc3);
            acc0 = fmaf(w.y, h1.x, acc0); acc1 = fmaf(w.y, h1.y, acc1);
            acc2 = fmaf(w.y, h1.z, acc2); acc3 = fmaf(w.y, h1.w, acc3);
            acc0 = fmaf(w.z, h2.x, acc0); acc1 = fmaf(w.z, h2.y, acc1);
            acc2 = fmaf(w.z, h2.z, acc2); acc3 = fmaf(w.z, h2.w, acc3);
            acc0 = fmaf(w.w, h3.x, acc0); acc1 = fmaf(w.w, h3.y, acc1);
            acc2 = fmaf(w.w, h3.z, acc2); acc3 = fmaf(w.w, h3.w, acc3);
        }
        out[(size_t)(b0 + r0 + 0) * NOUT + oc] = acc0;
        out[(size_t)(b0 + r0 + 1) * NOUT + oc] = acc1;
        out[(size_t)(b0 + r0 + 2) * NOUT + oc] = acc2;
        out[(size_t)(b0 + r0 + 3) * NOUT + oc] = acc3;
    }
}

extern "C" void kernel_launch(void* const* d_in, const int* in_sizes, int n_in,
                              void* d_out, int out_size)
{
    const float* x     = (const float*)d_in[0];
    const float* W_ih  = (const float*)d_in[1];
    const float* W_hh  = (const float*)d_in[2];
    const float* b_ih  = (const float*)d_in[3];
    const float* b_hh  = (const float*)d_in[4];
    const float* W_out = (const float*)d_in[5];
    const float* b_out = (const float*)d_in[6];
    float* out = (float*)d_out;

    prep_kernel<<<((NF + H) * G4 + 255) / 256, 256>>>(W_ih, W_hh);

    cudaFuncSetAttribute(lstm_kernel,
                         cudaFuncAttributeMaxDynamicSharedMemorySize, SMEM_BYTES);
    lstm_kernel<<<NCTA, NTHR, SMEM_BYTES>>>(x, b_ih, b_hh, W_out, b_out, out);
}